// round 12
// baseline (speedup 1.0000x reference)
#include <cuda_runtime.h>
#include <cuda_fp16.h>
#include <math.h>
#include <stdint.h>

// GMM_64003602645506 — warp-independent fp16 mma.sync GEMM, barrier-free.
// R12: single-wave schedule — 21 warps/CTA (672 thr), one 32-sample unit per
// warp (3192 warps >= 3125 units), static assignment, in-place epilogue to
// fit the 96-register cap.

#define D        32
#define K        64
#define NG       84
#define NKS      42
#define UNIT     32
#define TPB      672
#define NWARP    21
#define LOG_2PI  1.8378770664093453f

// smem layout (bytes)
#define SB_WORDS  (NKS * 4 * 32 * 4)          // 21504 uint32 (86016 B)
#define SB_OFF    0
#define XBUF_W    (UNIT * 20)                 // 640 uint32 per warp per parity
#define XE_OFF    86016
#define XO_OFF    (XE_OFF + NWARP * XBUF_W * 4)   // +53760
#define SLC_OFF   (XO_OFF + NWARP * XBUF_W * 4)   // 193536
#define SLW_OFF   (SLC_OFF + 256)
#define SGRP_OFF  (SLW_OFF + 256)
#define SMEM_TOTAL (SGRP_OFF + 512)

__device__ uint32_t g_Bfrag[SB_WORDS];
__device__ float  g_lc[K];
__device__ float  g_lwv[K];
__device__ double g_acc;
__device__ int    g_done;

__device__ __forceinline__ void gdecode(int g, int& e, int& d, bool& lin) {
    if (g >= 80) { lin = true; e = (g - 80) * 8; d = 0; return; }
    lin = false;
    if (g < 32)      { d = g >> 2;            e = (g & 3) * 8; }
    else if (g < 56) { d = 8 + (g - 32) / 3;  e = ((g - 32) % 3) * 8; }
    else if (g < 72) { d = 16 + ((g - 56) >> 1); e = ((g - 56) & 1) * 8; }
    else             { d = 24 + (g - 72);     e = 0; }
}

__device__ __forceinline__ uint32_t hmul2u(uint32_t a, uint32_t b) {
    __half2 r = __hmul2(*(__half2*)&a, *(__half2*)&b);
    return *(uint32_t*)&r;
}

__device__ __forceinline__ void mmaf16(float* c, uint32_t a0, uint32_t a1,
                                       uint32_t a2, uint32_t a3,
                                       uint32_t b0, uint32_t b1) {
    asm volatile(
        "mma.sync.aligned.m16n8k16.row.col.f32.f16.f16.f32 "
        "{%0,%1,%2,%3}, {%4,%5,%6,%7}, {%8,%9}, {%0,%1,%2,%3};"
        : "+f"(c[0]), "+f"(c[1]), "+f"(c[2]), "+f"(c[3])
        : "r"(a0), "r"(a1), "r"(a2), "r"(a3), "r"(b0), "r"(b1));
}

// ---------------------------------------------------------------------------
// Prep: 64 blocks x 128 threads (R11 — validated).
// ---------------------------------------------------------------------------
__global__ void prep_kernel(const float* __restrict__ means,
                            const float* __restrict__ scale_tril,
                            const float* __restrict__ log_weights) {
    int k = blockIdx.x, t = threadIdx.x;
    __shared__ float Ls[D][D], As[D][D + 1], mu[D], u[D], b[D], rv[D];

    float hld = 0.0f, c = 0.0f, lse = 0.0f;

    for (int i = t; i < D * D; i += 128)
        Ls[i / D][i % D] = scale_tril[k * D * D + i];
    __syncthreads();

    if (t < 32) {
        mu[t] = means[k * D + t];
        rv[t] = 1.0f / Ls[t][t];
        __syncwarp();

        hld = logf(Ls[t][t]);
        #pragma unroll
        for (int o = 16; o; o >>= 1) hld += __shfl_xor_sync(~0u, hld, o);

        {
            float s[D];
            #pragma unroll
            for (int i = 0; i < D; i++) s[i] = 0.0f;
            #pragma unroll
            for (int j = 0; j < D; j++) {
                float del = (j == t) ? 1.0f : 0.0f;
                float aj = (del - s[j]) * rv[j];
                As[j][t] = aj;
                #pragma unroll
                for (int i = j + 1; i < D; i++)
                    s[i] = fmaf(Ls[i][j], aj, s[i]);
            }
        }
        __syncwarp();

        { float s = 0.0f; for (int j = 0; j <= t; j++) s += As[t][j] * mu[j]; u[t] = s; }
        __syncwarp();
        { float s = 0.0f; for (int r = t; r < D; r++) s += As[r][t] * u[r]; b[t] = s; }
        __syncwarp();
        c = b[t] * mu[t];
        #pragma unroll
        for (int o = 16; o; o >>= 1) c += __shfl_xor_sync(~0u, c, o);

        float v0 = log_weights[t], v1 = log_weights[t + 32];
        float mx = fmaxf(v0, v1);
        #pragma unroll
        for (int o = 16; o; o >>= 1) mx = fmaxf(mx, __shfl_xor_sync(~0u, mx, o));
        float se = expf(v0 - mx) + expf(v1 - mx);
        #pragma unroll
        for (int o = 16; o; o >>= 1) se += __shfl_xor_sync(~0u, se, o);
        lse = mx + logf(se);
    }
    __syncthreads();

    __half* Bh = (__half*)g_Bfrag;
    for (int idx = t; idx < NG * 8; idx += 128) {
        int g = idx >> 3, cc = idx & 7;
        int e, d; bool lin;
        gdecode(g, e, d, lin);
        float v;
        if (lin) {
            v = -2.0f * b[e + cc];
        } else {
            int i = e + cc, j = i + d;
            if (j > 31) v = 0.0f;
            else {
                float s = 0.0f;
                for (int r = j; r < D; r++) s += As[r][i] * As[r][j];
                v = (d == 0) ? s : 2.0f * s;
            }
        }
        int kk = (g & 1) * 8 + cc, s_ = g >> 1;
        int rr = kk >> 3, kkl = kk & 7, tt = kkl >> 1, hh = kkl & 1;
        int nt = k >> 3, q = nt >> 1, w = (nt & 1) * 2 + rr;
        int L = (k & 7) * 4 + tt;
        Bh[((((s_ * 4 + q) * 32 + L) * 4) + w) * 2 + hh] = __float2half(v);
    }

    if (t == 0) {
        float lwk = log_weights[k] - lse;
        g_lwv[k] = lwk;
        g_lc[k]  = -0.5f * (c + (float)D * LOG_2PI) - hld + lwk;
        if (k == 0) { g_acc = 0.0; g_done = 0; }
    }
}

// ---------------------------------------------------------------------------
// Main: persistent single wave — warp w of block b owns unit b*NWARP+w.
// ---------------------------------------------------------------------------
__global__ void __launch_bounds__(TPB, 1) gmm_main(const float* __restrict__ X,
                                                   float* __restrict__ out,
                                                   int N, int nunits) {
    extern __shared__ char smem[];
    const int tid = threadIdx.x;
    const int wid = tid >> 5;
    const int lane = tid & 31;
    const int gq = lane >> 2;
    const int t  = lane & 3;

    float* sLC = (float*)(smem + SLC_OFF);
    float* sLW = (float*)(smem + SLW_OFF);
    uint32_t* sGrp = (uint32_t*)(smem + SGRP_OFF);
    const uint4* sB4 = (const uint4*)(smem + SB_OFF);

    for (int i = tid; i < SB_WORDS; i += TPB)
        ((uint32_t*)(smem + SB_OFF))[i] = g_Bfrag[i];
    if (tid < K) { sLC[tid] = g_lc[tid]; sLW[tid] = g_lwv[tid]; }
    if (tid < NG) {
        int e, d; bool lin;
        gdecode(tid, e, d, lin);
        int j2 = e + d;
        sGrp[tid] = (uint32_t)(e >> 1) | ((uint32_t)(j2 >> 1) << 8)
                  | ((uint32_t)(j2 & 1) << 16) | (lin ? (1u << 17) : 0u);
    }
    if (tid >= NG && tid < NG + 2) sGrp[tid] = 0u;
    __syncthreads();

    uint32_t* xe = (uint32_t*)(smem + XE_OFF) + wid * XBUF_W;
    uint32_t* xo = (uint32_t*)(smem + XO_OFF) + wid * XBUF_W;

    const int rb00 = gq * 20 + t;
    const int rb01 = (gq + 8) * 20 + t;
    const int rb10 = (gq + 16) * 20 + t;
    const int rb11 = (gq + 24) * 20 + t;

    const int twarps = (int)gridDim.x * NWARP;
    float accf = 0.0f;

    for (int u = (int)blockIdx.x * NWARP + wid; u < nunits; u += twarps) {
        const int base = u * UNIT;

        // stage x: lane handles row = lane
        {
            int row = lane;
            int n = base + row;
            float xv[33];
            if (n < N) {
                const float4* xp = (const float4*)X + (size_t)n * 8;
                #pragma unroll
                for (int v = 0; v < 8; v++) {
                    float4 f4 = xp[v];
                    xv[4*v] = f4.x; xv[4*v+1] = f4.y;
                    xv[4*v+2] = f4.z; xv[4*v+3] = f4.w;
                }
            } else {
                #pragma unroll
                for (int i = 0; i < D; i++) xv[i] = 0.0f;
            }
            xv[32] = 0.0f;
            uint32_t* xer = xe + row * 20;
            uint32_t* xor_ = xo + row * 20;
            #pragma unroll
            for (int p = 0; p < 16; p++) {
                __half2 h = __floats2half2_rn(xv[2*p], xv[2*p+1]);
                xer[p] = *(uint32_t*)&h;
                __half2 ho = __floats2half2_rn(xv[2*p+1], xv[2*p+2]);
                xor_[p] = *(uint32_t*)&ho;
            }
            #pragma unroll
            for (int p = 16; p < 20; p++) { xer[p] = 0u; xor_[p] = 0u; }
        }
        __syncwarp();

        float acc[2][8][4];
        #pragma unroll
        for (int m = 0; m < 2; m++)
            #pragma unroll
            for (int nt = 0; nt < 8; nt++)
                #pragma unroll
                for (int r = 0; r < 4; r++) acc[m][nt][r] = 0.0f;

        uint32_t mE = sGrp[0], mO = sGrp[1];
        for (int s = 0; s < NKS; s++) {
            const uint32_t gE = mE, gO = mO;
            mE = sGrp[2 * s + 2];
            mO = sGrp[2 * s + 3];

            const int p1E = gE & 0xff, p2E = (gE >> 8) & 0xff;
            const int p1O = gO & 0xff, p2O = (gO >> 8) & 0xff;
            const uint32_t* x2E = ((gE >> 16) & 1) ? xo : xe;
            const uint32_t* x2O = ((gO >> 16) & 1) ? xo : xe;
            const bool linE = (gE >> 17) & 1, linO = (gO >> 17) & 1;

            uint32_t a0[2], a1[2], a2[2], a3[2];
            // m-tile 0 (rows gq, gq+8)
            {
                uint32_t e1a = xe[rb00 + p1E], e2a = x2E[rb00 + p2E];
                uint32_t e1b = xe[rb01 + p1E], e2b = x2E[rb01 + p2E];
                uint32_t e1c = xe[rb00 + p1O], e2c = x2O[rb00 + p2O];
                uint32_t e1d = xe[rb01 + p1O], e2d = x2O[rb01 + p2O];
                a0[0] = linE ? e1a : hmul2u(e1a, e2a);
                a1[0] = linE ? e1b : hmul2u(e1b, e2b);
                a2[0] = linO ? e1c : hmul2u(e1c, e2c);
                a3[0] = linO ? e1d : hmul2u(e1d, e2d);
            }
            // m-tile 1 (rows gq+16, gq+24)
            {
                uint32_t e1a = xe[rb10 + p1E], e2a = x2E[rb10 + p2E];
                uint32_t e1b = xe[rb11 + p1E], e2b = x2E[rb11 + p2E];
                uint32_t e1c = xe[rb10 + p1O], e2c = x2O[rb10 + p2O];
                uint32_t e1d = xe[rb11 + p1O], e2d = x2O[rb11 + p2O];
                a0[1] = linE ? e1a : hmul2u(e1a, e2a);
                a1[1] = linE ? e1b : hmul2u(e1b, e2b);
                a2[1] = linO ? e1c : hmul2u(e1c, e2c);
                a3[1] = linO ? e1d : hmul2u(e1d, e2d);
            }
            #pragma unroll
            for (int q = 0; q < 4; q++) {
                uint4 B = sB4[(s * 4 + q) * 32 + lane];
                #pragma unroll
                for (int m = 0; m < 2; m++) {
                    mmaf16(acc[m][2*q],   a0[m], a1[m], a2[m], a3[m], B.x, B.y);
                    mmaf16(acc[m][2*q+1], a0[m], a1[m], a2[m], a3[m], B.z, B.w);
                }
            }
        }

        // epilogue: in-place transform acc <- -0.5*acc + lc  (no extra glp[])
        #pragma unroll
        for (int m = 0; m < 2; m++)
            #pragma unroll
            for (int nt = 0; nt < 8; nt++)
                #pragma unroll
                for (int rh = 0; rh < 2; rh++)
                    #pragma unroll
                    for (int h = 0; h < 2; h++) {
                        int col = nt * 8 + 2 * t + h;
                        acc[m][nt][rh * 2 + h] =
                            fmaf(-0.5f, acc[m][nt][rh * 2 + h], sLC[col]);
                    }

        #pragma unroll
        for (int m = 0; m < 2; m++) {
            #pragma unroll
            for (int rh = 0; rh < 2; rh++) {
                int n = base + gq + 16 * m + 8 * rh;
                float mx = -1e30f;
                #pragma unroll
                for (int nt = 0; nt < 8; nt++) {
                    mx = fmaxf(mx, acc[m][nt][rh * 2]);
                    mx = fmaxf(mx, acc[m][nt][rh * 2 + 1]);
                }
                mx = fmaxf(mx, __shfl_xor_sync(~0u, mx, 1));
                mx = fmaxf(mx, __shfl_xor_sync(~0u, mx, 2));
                float S = 0.0f, T = 0.0f;
                #pragma unroll
                for (int nt = 0; nt < 8; nt++) {
                    #pragma unroll
                    for (int h = 0; h < 2; h++) {
                        int col = nt * 8 + 2 * t + h;
                        float g = acc[m][nt][rh * 2 + h];
                        float e = __expf(g - mx);
                        S += e;
                        T = fmaf(e, g - sLW[col], T);
                    }
                }
                S += __shfl_xor_sync(~0u, S, 1);
                S += __shfl_xor_sync(~0u, S, 2);
                T += __shfl_xor_sync(~0u, T, 1);
                T += __shfl_xor_sync(~0u, T, 2);
                if (t == 0 && n < N) accf += T / S;
            }
        }
    }

    #pragma unroll
    for (int o = 16; o; o >>= 1) accf += __shfl_xor_sync(~0u, accf, o);
    if (lane == 0) atomicAdd(&g_acc, (double)accf);

    __syncthreads();
    __threadfence();
    if (tid == 0) {
        if (atomicAdd(&g_done, 1) == (int)gridDim.x - 1) {
            double total = atomicAdd(&g_acc, 0.0);
            out[0] = (float)(-total / (double)N);
        }
    }
}

// ---------------------------------------------------------------------------
extern "C" void kernel_launch(void* const* d_in, const int* in_sizes, int n_in,
                              void* d_out, int out_size) {
    const float* X           = (const float*)d_in[0];
    const float* means       = (const float*)d_in[1];
    const float* scale_tril  = (const float*)d_in[2];
    const float* log_weights = (const float*)d_in[3];
    float* out = (float*)d_out;

    int N = in_sizes[0] / D;
    int nunits = (N + UNIT - 1) / UNIT;

    cudaFuncSetAttribute(gmm_main, cudaFuncAttributeMaxDynamicSharedMemorySize,
                         SMEM_TOTAL);
    int nsm = 148;
    cudaDeviceGetAttribute(&nsm, cudaDevAttrMultiProcessorCount, 0);

    prep_kernel<<<K, 128>>>(means, scale_tril, log_weights);
    gmm_main<<<nsm, TPB, SMEM_TOTAL>>>(X, out, N, nunits);
}

// round 14
// speedup vs baseline: 1.0375x; 1.0375x over previous
#include <cuda_runtime.h>
#include <cuda_fp16.h>
#include <math.h>
#include <stdint.h>

// GMM_64003602645506 — warp-independent fp16 mma.sync GEMM, barrier-free.
// R14: R13 fusion with LEGAL barriers — prep_body entered by ALL threads of
// CTAs 0..63 (work guarded inside; __syncthreads block-uniform). 17 warps.

#define D        32
#define K        64
#define NG       84
#define NKS      42
#define UNIT     32
#define TPB      544
#define NWARP    17
#define LOG_2PI  1.8378770664093453f

// smem layout (bytes)
#define SB_WORDS  (NKS * 4 * 32 * 4)          // 21504 uint32 (86016 B)
#define SB_OFF    0
#define XBUF_W    (UNIT * 20)                 // 640 uint32 per warp per parity
#define XE_OFF    86016
#define XO_OFF    (XE_OFF + NWARP * XBUF_W * 4)
#define SLC_OFF   (XO_OFF + NWARP * XBUF_W * 4)
#define SLW_OFF   (SLC_OFF + 256)
#define SGRP_OFF  (SLW_OFF + 256)
#define SMEM_TOTAL (SGRP_OFF + 512)

__device__ uint32_t g_Bfrag[SB_WORDS];
__device__ float  g_lc[K];
__device__ float  g_lwv[K];
__device__ double g_acc;
__device__ int    g_counter;
__device__ int    g_done;
__device__ int    g_prep_done;

__device__ __forceinline__ void gdecode(int g, int& e, int& d, bool& lin) {
    if (g >= 80) { lin = true; e = (g - 80) * 8; d = 0; return; }
    lin = false;
    if (g < 32)      { d = g >> 2;            e = (g & 3) * 8; }
    else if (g < 56) { d = 8 + (g - 32) / 3;  e = ((g - 32) % 3) * 8; }
    else if (g < 72) { d = 16 + ((g - 56) >> 1); e = ((g - 56) & 1) * 8; }
    else             { d = 24 + (g - 72);     e = 0; }
}

__device__ __forceinline__ uint32_t hmul2u(uint32_t a, uint32_t b) {
    __half2 r = __hmul2(*(__half2*)&a, *(__half2*)&b);
    return *(uint32_t*)&r;
}

__device__ __forceinline__ void mmaf16(float* c, uint32_t a0, uint32_t a1,
                                       uint32_t a2, uint32_t a3,
                                       uint32_t b0, uint32_t b1) {
    asm volatile(
        "mma.sync.aligned.m16n8k16.row.col.f32.f16.f16.f32 "
        "{%0,%1,%2,%3}, {%4,%5,%6,%7}, {%8,%9}, {%0,%1,%2,%3};"
        : "+f"(c[0]), "+f"(c[1]), "+f"(c[2]), "+f"(c[3])
        : "r"(a0), "r"(a1), "r"(a2), "r"(a3), "r"(b0), "r"(b1));
}

// ---------------------------------------------------------------------------
// Prep body: entered by ALL TPB threads of CTAs 0..63 (k = blockIdx.x).
// All __syncthreads() are block-uniform; compute guarded inside.
// ---------------------------------------------------------------------------
__device__ void prep_body(char* smem, int k, int tid,
                          const float* __restrict__ means,
                          const float* __restrict__ scale_tril,
                          const float* __restrict__ log_weights) {
    float (*Ls)[D]     = (float(*)[D])(smem);
    float (*As)[D + 1] = (float(*)[D + 1])(smem + 4096);
    float* mu = (float*)(smem + 8448);
    float* u  = (float*)(smem + 8448 + 128);
    float* b  = (float*)(smem + 8448 + 256);
    float* rv = (float*)(smem + 8448 + 384);

    for (int i = tid; i < D * D; i += TPB)
        Ls[i / D][i % D] = scale_tril[k * D * D + i];
    __syncthreads();

    float hld = 0.0f, c = 0.0f, lse = 0.0f;
    if (tid < 32) {                       // whole warp 0: __syncwarp legal
        int t = tid;
        mu[t] = means[k * D + t];
        rv[t] = 1.0f / Ls[t][t];
        __syncwarp();

        hld = logf(Ls[t][t]);
        #pragma unroll
        for (int o = 16; o; o >>= 1) hld += __shfl_xor_sync(~0u, hld, o);

        {
            float s[D];
            #pragma unroll
            for (int i = 0; i < D; i++) s[i] = 0.0f;
            #pragma unroll
            for (int j = 0; j < D; j++) {
                float del = (j == t) ? 1.0f : 0.0f;
                float aj = (del - s[j]) * rv[j];
                As[j][t] = aj;
                #pragma unroll
                for (int i = j + 1; i < D; i++)
                    s[i] = fmaf(Ls[i][j], aj, s[i]);
            }
        }
        __syncwarp();

        { float s = 0.0f; for (int j = 0; j <= t; j++) s += As[t][j] * mu[j]; u[t] = s; }
        __syncwarp();
        { float s = 0.0f; for (int r = t; r < D; r++) s += As[r][t] * u[r]; b[t] = s; }
        __syncwarp();
        c = b[t] * mu[t];
        #pragma unroll
        for (int o = 16; o; o >>= 1) c += __shfl_xor_sync(~0u, c, o);

        float v0 = log_weights[t], v1 = log_weights[t + 32];
        float mx = fmaxf(v0, v1);
        #pragma unroll
        for (int o = 16; o; o >>= 1) mx = fmaxf(mx, __shfl_xor_sync(~0u, mx, o));
        float se = expf(v0 - mx) + expf(v1 - mx);
        #pragma unroll
        for (int o = 16; o; o >>= 1) se += __shfl_xor_sync(~0u, se, o);
        lse = mx + logf(se);
    }
    __syncthreads();

    __half* Bh = (__half*)g_Bfrag;
    for (int idx = tid; idx < NG * 8; idx += TPB) {
        int g = idx >> 3, cc = idx & 7;
        int e, d; bool lin;
        gdecode(g, e, d, lin);
        float v;
        if (lin) {
            v = -2.0f * b[e + cc];
        } else {
            int i = e + cc, j = i + d;
            if (j > 31) v = 0.0f;
            else {
                float s = 0.0f;
                for (int r = j; r < D; r++) s += As[r][i] * As[r][j];
                v = (d == 0) ? s : 2.0f * s;
            }
        }
        int kk = (g & 1) * 8 + cc, s_ = g >> 1;
        int rr = kk >> 3, kkl = kk & 7, tt = kkl >> 1, hh = kkl & 1;
        int nt = k >> 3, q = nt >> 1, w = (nt & 1) * 2 + rr;
        int L = (k & 7) * 4 + tt;
        Bh[((((s_ * 4 + q) * 32 + L) * 4) + w) * 2 + hh] = __float2half(v);
    }

    if (tid == 0) {
        float lwk = log_weights[k] - lse;
        g_lwv[k] = lwk;
        g_lc[k]  = -0.5f * (c + (float)D * LOG_2PI) - hld + lwk;
    }
    __syncthreads();                       // emission done before flag
    if (tid == 0) {
        __threadfence();
        atomicAdd(&g_prep_done, 1);
    }
}

// ---------------------------------------------------------------------------
// Fused kernel: prep (CTAs 0..63, all threads) -> co-resident spin -> GEMM.
// ---------------------------------------------------------------------------
__global__ void __launch_bounds__(TPB, 1) gmm_fused(
        const float* __restrict__ X,
        const float* __restrict__ means,
        const float* __restrict__ scale_tril,
        const float* __restrict__ log_weights,
        float* __restrict__ out, int N, int nunits) {
    extern __shared__ char smem[];
    const int tid = threadIdx.x;
    const int wid = tid >> 5;
    const int lane = tid & 31;
    const int gq = lane >> 2;
    const int t  = lane & 3;

    // ---- phase 0: prep (block-uniform participation) ----
    if (blockIdx.x < 64)
        prep_body(smem, blockIdx.x, tid, means, scale_tril, log_weights);

    // wait for all 64 prep blocks (co-resident grid -> no deadlock)
    if (tid == 0) {
        while (atomicAdd(&g_prep_done, 0) < 64) { }
    }
    __syncthreads();

    // ---- phase 1: smem init ----
    float* sLC = (float*)(smem + SLC_OFF);
    float* sLW = (float*)(smem + SLW_OFF);
    uint32_t* sGrp = (uint32_t*)(smem + SGRP_OFF);
    const uint4* sB4 = (const uint4*)(smem + SB_OFF);

    for (int i = tid; i < SB_WORDS; i += TPB)
        ((uint32_t*)(smem + SB_OFF))[i] = g_Bfrag[i];
    if (tid < K) { sLC[tid] = g_lc[tid]; sLW[tid] = g_lwv[tid]; }
    if (tid < NG) {
        int e, d; bool lin;
        gdecode(tid, e, d, lin);
        int j2 = e + d;
        sGrp[tid] = (uint32_t)(e >> 1) | ((uint32_t)(j2 >> 1) << 8)
                  | ((uint32_t)(j2 & 1) << 16) | (lin ? (1u << 17) : 0u);
    }
    if (tid >= NG && tid < NG + 2) sGrp[tid] = 0u;
    __syncthreads();

    uint32_t* xe = (uint32_t*)(smem + XE_OFF) + wid * XBUF_W;
    uint32_t* xo = (uint32_t*)(smem + XO_OFF) + wid * XBUF_W;

    int rb[2][2];
    #pragma unroll
    for (int m = 0; m < 2; m++) {
        rb[m][0] = (gq + 16 * m) * 20 + t;
        rb[m][1] = (gq + 16 * m + 8) * 20 + t;
    }

    float accf = 0.0f;

    // ---- phase 2: persistent GEMM, warp-level stealing (R11 verbatim) ----
    for (;;) {
        int u;
        if (lane == 0) u = atomicAdd(&g_counter, 1);
        u = __shfl_sync(~0u, u, 0);
        if (u >= nunits) break;
        const int base = u * UNIT;

        __syncwarp();
        {
            int row = lane;
            int n = base + row;
            float xv[33];
            if (n < N) {
                const float4* xp = (const float4*)X + (size_t)n * 8;
                #pragma unroll
                for (int v = 0; v < 8; v++) {
                    float4 f4 = xp[v];
                    xv[4*v] = f4.x; xv[4*v+1] = f4.y;
                    xv[4*v+2] = f4.z; xv[4*v+3] = f4.w;
                }
            } else {
                #pragma unroll
                for (int i = 0; i < D; i++) xv[i] = 0.0f;
            }
            xv[32] = 0.0f;
            uint32_t* xer = xe + row * 20;
            uint32_t* xor_ = xo + row * 20;
            #pragma unroll
            for (int p = 0; p < 16; p++) {
                __half2 h = __floats2half2_rn(xv[2*p], xv[2*p+1]);
                xer[p] = *(uint32_t*)&h;
                __half2 ho = __floats2half2_rn(xv[2*p+1], xv[2*p+2]);
                xor_[p] = *(uint32_t*)&ho;
            }
            #pragma unroll
            for (int p = 16; p < 20; p++) { xer[p] = 0u; xor_[p] = 0u; }
        }
        __syncwarp();

        float acc[2][8][4];
        #pragma unroll
        for (int m = 0; m < 2; m++)
            #pragma unroll
            for (int nt = 0; nt < 8; nt++)
                #pragma unroll
                for (int r = 0; r < 4; r++) acc[m][nt][r] = 0.0f;

        uint32_t mE = sGrp[0], mO = sGrp[1];
        for (int s = 0; s < NKS; s++) {
            const uint32_t gE = mE, gO = mO;
            mE = sGrp[2 * s + 2];
            mO = sGrp[2 * s + 3];

            const int p1E = gE & 0xff, p2E = (gE >> 8) & 0xff;
            const int p1O = gO & 0xff, p2O = (gO >> 8) & 0xff;
            const uint32_t* x2E = ((gE >> 16) & 1) ? xo : xe;
            const uint32_t* x2O = ((gO >> 16) & 1) ? xo : xe;
            const bool linE = (gE >> 17) & 1, linO = (gO >> 17) & 1;

            uint32_t e1a = xe[rb[0][0] + p1E], e2a = x2E[rb[0][0] + p2E];
            uint32_t e1b = xe[rb[0][1] + p1E], e2b = x2E[rb[0][1] + p2E];
            uint32_t e1c = xe[rb[0][0] + p1O], e2c = x2O[rb[0][0] + p2O];
            uint32_t e1d = xe[rb[0][1] + p1O], e2d = x2O[rb[0][1] + p2O];
            uint32_t f1a = xe[rb[1][0] + p1E], f2a = x2E[rb[1][0] + p2E];
            uint32_t f1b = xe[rb[1][1] + p1E], f2b = x2E[rb[1][1] + p2E];
            uint32_t f1c = xe[rb[1][0] + p1O], f2c = x2O[rb[1][0] + p2O];
            uint32_t f1d = xe[rb[1][1] + p1O], f2d = x2O[rb[1][1] + p2O];

            uint32_t a0[2], a1[2], a2[2], a3[2];
            a0[0] = linE ? e1a : hmul2u(e1a, e2a);
            a1[0] = linE ? e1b : hmul2u(e1b, e2b);
            a2[0] = linO ? e1c : hmul2u(e1c, e2c);
            a3[0] = linO ? e1d : hmul2u(e1d, e2d);
            a0[1] = linE ? f1a : hmul2u(f1a, f2a);
            a1[1] = linE ? f1b : hmul2u(f1b, f2b);
            a2[1] = linO ? f1c : hmul2u(f1c, f2c);
            a3[1] = linO ? f1d : hmul2u(f1d, f2d);

            #pragma unroll
            for (int q = 0; q < 4; q++) {
                uint4 B = sB4[(s * 4 + q) * 32 + lane];
                #pragma unroll
                for (int m = 0; m < 2; m++) {
                    mmaf16(acc[m][2*q],   a0[m], a1[m], a2[m], a3[m], B.x, B.y);
                    mmaf16(acc[m][2*q+1], a0[m], a1[m], a2[m], a3[m], B.z, B.w);
                }
            }
        }

        // epilogue
        #pragma unroll
        for (int m = 0; m < 2; m++) {
            #pragma unroll
            for (int rh = 0; rh < 2; rh++) {
                int n = base + gq + 16 * m + 8 * rh;
                float glp[16], mx = -1e30f;
                #pragma unroll
                for (int nt = 0; nt < 8; nt++) {
                    #pragma unroll
                    for (int h = 0; h < 2; h++) {
                        int col = nt * 8 + 2 * t + h;
                        float g = fmaf(-0.5f, acc[m][nt][rh * 2 + h], sLC[col]);
                        glp[nt * 2 + h] = g;
                        mx = fmaxf(mx, g);
                    }
                }
                mx = fmaxf(mx, __shfl_xor_sync(~0u, mx, 1));
                mx = fmaxf(mx, __shfl_xor_sync(~0u, mx, 2));
                float S = 0.0f, T = 0.0f;
                #pragma unroll
                for (int nt = 0; nt < 8; nt++) {
                    #pragma unroll
                    for (int h = 0; h < 2; h++) {
                        int col = nt * 8 + 2 * t + h;
                        float e = __expf(glp[nt * 2 + h] - mx);
                        S += e;
                        T = fmaf(e, glp[nt * 2 + h] - sLW[col], T);
                    }
                }
                S += __shfl_xor_sync(~0u, S, 1);
                S += __shfl_xor_sync(~0u, S, 2);
                T += __shfl_xor_sync(~0u, T, 1);
                T += __shfl_xor_sync(~0u, T, 2);
                if (t == 0 && n < N) accf += T / S;
            }
        }
    }

    #pragma unroll
    for (int o = 16; o; o >>= 1) accf += __shfl_xor_sync(~0u, accf, o);
    if (lane == 0) atomicAdd(&g_acc, (double)accf);

    __syncthreads();
    __threadfence();
    if (tid == 0) {
        if (atomicAdd(&g_done, 1) == (int)gridDim.x - 1) {
            double total = atomicAdd(&g_acc, 0.0);
            out[0] = (float)(-total / (double)N);
            // reset for next graph replay (all other CTAs already finished)
            g_acc = 0.0;
            g_counter = 0;
            g_prep_done = 0;
            g_done = 0;
            __threadfence();
        }
    }
}

// ---------------------------------------------------------------------------
extern "C" void kernel_launch(void* const* d_in, const int* in_sizes, int n_in,
                              void* d_out, int out_size) {
    const float* X           = (const float*)d_in[0];
    const float* means       = (const float*)d_in[1];
    const float* scale_tril  = (const float*)d_in[2];
    const float* log_weights = (const float*)d_in[3];
    float* out = (float*)d_out;

    int N = in_sizes[0] / D;
    int nunits = (N + UNIT - 1) / UNIT;

    cudaFuncSetAttribute(gmm_fused, cudaFuncAttributeMaxDynamicSharedMemorySize,
                         SMEM_TOTAL);
    int nsm = 148;
    cudaDeviceGetAttribute(&nsm, cudaDevAttrMultiProcessorCount, 0);

    gmm_fused<<<nsm, TPB, SMEM_TOTAL>>>(X, means, scale_tril, log_weights,
                                        out, N, nunits);
}

// round 15
// speedup vs baseline: 1.2249x; 1.1806x over previous
#include <cuda_runtime.h>
#include <cuda_fp16.h>
#include <math.h>
#include <stdint.h>

// GMM_64003602645506 — warp-independent fp16 mma.sync GEMM, barrier-free.
// R15: R14 fusion (legal barriers) at TPB=512 — the validated 119-register
// ILP operating point of the R11 mainloop. 16 warps/CTA, UNIT=32.

#define D        32
#define K        64
#define NG       84
#define NKS      42
#define UNIT     32
#define TPB      512
#define NWARP    16
#define LOG_2PI  1.8378770664093453f

// smem layout (bytes)
#define SB_WORDS  (NKS * 4 * 32 * 4)          // 21504 uint32 (86016 B)
#define SB_OFF    0
#define XBUF_W    (UNIT * 20)                 // 640 uint32 per warp per parity
#define XE_OFF    86016
#define XO_OFF    (XE_OFF + NWARP * XBUF_W * 4)   // 126976
#define SLC_OFF   (XO_OFF + NWARP * XBUF_W * 4)   // 167936
#define SLW_OFF   (SLC_OFF + 256)
#define SGRP_OFF  (SLW_OFF + 256)
#define SMEM_TOTAL (SGRP_OFF + 512)

__device__ uint32_t g_Bfrag[SB_WORDS];
__device__ float  g_lc[K];
__device__ float  g_lwv[K];
__device__ double g_acc;
__device__ int    g_counter;
__device__ int    g_done;
__device__ int    g_prep_done;

__device__ __forceinline__ void gdecode(int g, int& e, int& d, bool& lin) {
    if (g >= 80) { lin = true; e = (g - 80) * 8; d = 0; return; }
    lin = false;
    if (g < 32)      { d = g >> 2;            e = (g & 3) * 8; }
    else if (g < 56) { d = 8 + (g - 32) / 3;  e = ((g - 32) % 3) * 8; }
    else if (g < 72) { d = 16 + ((g - 56) >> 1); e = ((g - 56) & 1) * 8; }
    else             { d = 24 + (g - 72);     e = 0; }
}

__device__ __forceinline__ uint32_t hmul2u(uint32_t a, uint32_t b) {
    __half2 r = __hmul2(*(__half2*)&a, *(__half2*)&b);
    return *(uint32_t*)&r;
}

__device__ __forceinline__ void mmaf16(float* c, uint32_t a0, uint32_t a1,
                                       uint32_t a2, uint32_t a3,
                                       uint32_t b0, uint32_t b1) {
    asm volatile(
        "mma.sync.aligned.m16n8k16.row.col.f32.f16.f16.f32 "
        "{%0,%1,%2,%3}, {%4,%5,%6,%7}, {%8,%9}, {%0,%1,%2,%3};"
        : "+f"(c[0]), "+f"(c[1]), "+f"(c[2]), "+f"(c[3])
        : "r"(a0), "r"(a1), "r"(a2), "r"(a3), "r"(b0), "r"(b1));
}

// ---------------------------------------------------------------------------
// Prep body: entered by ALL TPB threads of CTAs 0..63 (k = blockIdx.x).
// Block-uniform __syncthreads; compute guarded inside.
// ---------------------------------------------------------------------------
__device__ void prep_body(char* smem, int k, int tid,
                          const float* __restrict__ means,
                          const float* __restrict__ scale_tril,
                          const float* __restrict__ log_weights) {
    float (*Ls)[D]     = (float(*)[D])(smem);
    float (*As)[D + 1] = (float(*)[D + 1])(smem + 4096);
    float* mu = (float*)(smem + 8448);
    float* u  = (float*)(smem + 8448 + 128);
    float* b  = (float*)(smem + 8448 + 256);
    float* rv = (float*)(smem + 8448 + 384);

    for (int i = tid; i < D * D; i += TPB)
        Ls[i / D][i % D] = scale_tril[k * D * D + i];
    __syncthreads();

    float hld = 0.0f, c = 0.0f, lse = 0.0f;
    if (tid < 32) {
        int t = tid;
        mu[t] = means[k * D + t];
        rv[t] = 1.0f / Ls[t][t];
        __syncwarp();

        hld = logf(Ls[t][t]);
        #pragma unroll
        for (int o = 16; o; o >>= 1) hld += __shfl_xor_sync(~0u, hld, o);

        {
            float s[D];
            #pragma unroll
            for (int i = 0; i < D; i++) s[i] = 0.0f;
            #pragma unroll
            for (int j = 0; j < D; j++) {
                float del = (j == t) ? 1.0f : 0.0f;
                float aj = (del - s[j]) * rv[j];
                As[j][t] = aj;
                #pragma unroll
                for (int i = j + 1; i < D; i++)
                    s[i] = fmaf(Ls[i][j], aj, s[i]);
            }
        }
        __syncwarp();

        { float s = 0.0f; for (int j = 0; j <= t; j++) s += As[t][j] * mu[j]; u[t] = s; }
        __syncwarp();
        { float s = 0.0f; for (int r = t; r < D; r++) s += As[r][t] * u[r]; b[t] = s; }
        __syncwarp();
        c = b[t] * mu[t];
        #pragma unroll
        for (int o = 16; o; o >>= 1) c += __shfl_xor_sync(~0u, c, o);

        float v0 = log_weights[t], v1 = log_weights[t + 32];
        float mx = fmaxf(v0, v1);
        #pragma unroll
        for (int o = 16; o; o >>= 1) mx = fmaxf(mx, __shfl_xor_sync(~0u, mx, o));
        float se = expf(v0 - mx) + expf(v1 - mx);
        #pragma unroll
        for (int o = 16; o; o >>= 1) se += __shfl_xor_sync(~0u, se, o);
        lse = mx + logf(se);
    }
    __syncthreads();

    __half* Bh = (__half*)g_Bfrag;
    for (int idx = tid; idx < NG * 8; idx += TPB) {
        int g = idx >> 3, cc = idx & 7;
        int e, d; bool lin;
        gdecode(g, e, d, lin);
        float v;
        if (lin) {
            v = -2.0f * b[e + cc];
        } else {
            int i = e + cc, j = i + d;
            if (j > 31) v = 0.0f;
            else {
                float s = 0.0f;
                for (int r = j; r < D; r++) s += As[r][i] * As[r][j];
                v = (d == 0) ? s : 2.0f * s;
            }
        }
        int kk = (g & 1) * 8 + cc, s_ = g >> 1;
        int rr = kk >> 3, kkl = kk & 7, tt = kkl >> 1, hh = kkl & 1;
        int nt = k >> 3, q = nt >> 1, w = (nt & 1) * 2 + rr;
        int L = (k & 7) * 4 + tt;
        Bh[((((s_ * 4 + q) * 32 + L) * 4) + w) * 2 + hh] = __float2half(v);
    }

    if (tid == 0) {
        float lwk = log_weights[k] - lse;
        g_lwv[k] = lwk;
        g_lc[k]  = -0.5f * (c + (float)D * LOG_2PI) - hld + lwk;
    }
    __syncthreads();
    if (tid == 0) {
        __threadfence();
        atomicAdd(&g_prep_done, 1);
    }
}

// ---------------------------------------------------------------------------
// Fused kernel: prep (CTAs 0..63) -> co-resident spin -> persistent GEMM.
// ---------------------------------------------------------------------------
__global__ void __launch_bounds__(TPB, 1) gmm_fused(
        const float* __restrict__ X,
        const float* __restrict__ means,
        const float* __restrict__ scale_tril,
        const float* __restrict__ log_weights,
        float* __restrict__ out, int N, int nunits) {
    extern __shared__ char smem[];
    const int tid = threadIdx.x;
    const int wid = tid >> 5;
    const int lane = tid & 31;
    const int gq = lane >> 2;
    const int t  = lane & 3;

    if (blockIdx.x < 64)
        prep_body(smem, blockIdx.x, tid, means, scale_tril, log_weights);

    if (tid == 0) {
        while (atomicAdd(&g_prep_done, 0) < 64) { }
    }
    __syncthreads();

    float* sLC = (float*)(smem + SLC_OFF);
    float* sLW = (float*)(smem + SLW_OFF);
    uint32_t* sGrp = (uint32_t*)(smem + SGRP_OFF);
    const uint4* sB4 = (const uint4*)(smem + SB_OFF);

    for (int i = tid; i < SB_WORDS; i += TPB)
        ((uint32_t*)(smem + SB_OFF))[i] = g_Bfrag[i];
    if (tid < K) { sLC[tid] = g_lc[tid]; sLW[tid] = g_lwv[tid]; }
    if (tid < NG) {
        int e, d; bool lin;
        gdecode(tid, e, d, lin);
        int j2 = e + d;
        sGrp[tid] = (uint32_t)(e >> 1) | ((uint32_t)(j2 >> 1) << 8)
                  | ((uint32_t)(j2 & 1) << 16) | (lin ? (1u << 17) : 0u);
    }
    if (tid >= NG && tid < NG + 2) sGrp[tid] = 0u;
    __syncthreads();

    uint32_t* xe = (uint32_t*)(smem + XE_OFF) + wid * XBUF_W;
    uint32_t* xo = (uint32_t*)(smem + XO_OFF) + wid * XBUF_W;

    int rb[2][2];
    #pragma unroll
    for (int m = 0; m < 2; m++) {
        rb[m][0] = (gq + 16 * m) * 20 + t;
        rb[m][1] = (gq + 16 * m + 8) * 20 + t;
    }

    float accf = 0.0f;

    for (;;) {
        int u;
        if (lane == 0) u = atomicAdd(&g_counter, 1);
        u = __shfl_sync(~0u, u, 0);
        if (u >= nunits) break;
        const int base = u * UNIT;

        __syncwarp();
        {
            int row = lane;
            int n = base + row;
            float xv[33];
            if (n < N) {
                const float4* xp = (const float4*)X + (size_t)n * 8;
                #pragma unroll
                for (int v = 0; v < 8; v++) {
                    float4 f4 = xp[v];
                    xv[4*v] = f4.x; xv[4*v+1] = f4.y;
                    xv[4*v+2] = f4.z; xv[4*v+3] = f4.w;
                }
            } else {
                #pragma unroll
                for (int i = 0; i < D; i++) xv[i] = 0.0f;
            }
            xv[32] = 0.0f;
            uint32_t* xer = xe + row * 20;
            uint32_t* xor_ = xo + row * 20;
            #pragma unroll
            for (int p = 0; p < 16; p++) {
                __half2 h = __floats2half2_rn(xv[2*p], xv[2*p+1]);
                xer[p] = *(uint32_t*)&h;
                __half2 ho = __floats2half2_rn(xv[2*p+1], xv[2*p+2]);
                xor_[p] = *(uint32_t*)&ho;
            }
            #pragma unroll
            for (int p = 16; p < 20; p++) { xer[p] = 0u; xor_[p] = 0u; }
        }
        __syncwarp();

        float acc[2][8][4];
        #pragma unroll
        for (int m = 0; m < 2; m++)
            #pragma unroll
            for (int nt = 0; nt < 8; nt++)
                #pragma unroll
                for (int r = 0; r < 4; r++) acc[m][nt][r] = 0.0f;

        uint32_t mE = sGrp[0], mO = sGrp[1];
        for (int s = 0; s < NKS; s++) {
            const uint32_t gE = mE, gO = mO;
            mE = sGrp[2 * s + 2];
            mO = sGrp[2 * s + 3];

            const int p1E = gE & 0xff, p2E = (gE >> 8) & 0xff;
            const int p1O = gO & 0xff, p2O = (gO >> 8) & 0xff;
            const uint32_t* x2E = ((gE >> 16) & 1) ? xo : xe;
            const uint32_t* x2O = ((gO >> 16) & 1) ? xo : xe;
            const bool linE = (gE >> 17) & 1, linO = (gO >> 17) & 1;

            uint32_t e1a = xe[rb[0][0] + p1E], e2a = x2E[rb[0][0] + p2E];
            uint32_t e1b = xe[rb[0][1] + p1E], e2b = x2E[rb[0][1] + p2E];
            uint32_t e1c = xe[rb[0][0] + p1O], e2c = x2O[rb[0][0] + p2O];
            uint32_t e1d = xe[rb[0][1] + p1O], e2d = x2O[rb[0][1] + p2O];
            uint32_t f1a = xe[rb[1][0] + p1E], f2a = x2E[rb[1][0] + p2E];
            uint32_t f1b = xe[rb[1][1] + p1E], f2b = x2E[rb[1][1] + p2E];
            uint32_t f1c = xe[rb[1][0] + p1O], f2c = x2O[rb[1][0] + p2O];
            uint32_t f1d = xe[rb[1][1] + p1O], f2d = x2O[rb[1][1] + p2O];

            uint32_t a0[2], a1[2], a2[2], a3[2];
            a0[0] = linE ? e1a : hmul2u(e1a, e2a);
            a1[0] = linE ? e1b : hmul2u(e1b, e2b);
            a2[0] = linO ? e1c : hmul2u(e1c, e2c);
            a3[0] = linO ? e1d : hmul2u(e1d, e2d);
            a0[1] = linE ? f1a : hmul2u(f1a, f2a);
            a1[1] = linE ? f1b : hmul2u(f1b, f2b);
            a2[1] = linO ? f1c : hmul2u(f1c, f2c);
            a3[1] = linO ? f1d : hmul2u(f1d, f2d);

            #pragma unroll
            for (int q = 0; q < 4; q++) {
                uint4 B = sB4[(s * 4 + q) * 32 + lane];
                #pragma unroll
                for (int m = 0; m < 2; m++) {
                    mmaf16(acc[m][2*q],   a0[m], a1[m], a2[m], a3[m], B.x, B.y);
                    mmaf16(acc[m][2*q+1], a0[m], a1[m], a2[m], a3[m], B.z, B.w);
                }
            }
        }

        #pragma unroll
        for (int m = 0; m < 2; m++) {
            #pragma unroll
            for (int rh = 0; rh < 2; rh++) {
                int n = base + gq + 16 * m + 8 * rh;
                float glp[16], mx = -1e30f;
                #pragma unroll
                for (int nt = 0; nt < 8; nt++) {
                    #pragma unroll
                    for (int h = 0; h < 2; h++) {
                        int col = nt * 8 + 2 * t + h;
                        float g = fmaf(-0.5f, acc[m][nt][rh * 2 + h], sLC[col]);
                        glp[nt * 2 + h] = g;
                        mx = fmaxf(mx, g);
                    }
                }
                mx = fmaxf(mx, __shfl_xor_sync(~0u, mx, 1));
                mx = fmaxf(mx, __shfl_xor_sync(~0u, mx, 2));
                float S = 0.0f, T = 0.0f;
                #pragma unroll
                for (int nt = 0; nt < 8; nt++) {
                    #pragma unroll
                    for (int h = 0; h < 2; h++) {
                        int col = nt * 8 + 2 * t + h;
                        float e = __expf(glp[nt * 2 + h] - mx);
                        S += e;
                        T = fmaf(e, glp[nt * 2 + h] - sLW[col], T);
                    }
                }
                S += __shfl_xor_sync(~0u, S, 1);
                S += __shfl_xor_sync(~0u, S, 2);
                T += __shfl_xor_sync(~0u, T, 1);
                T += __shfl_xor_sync(~0u, T, 2);
                if (t == 0 && n < N) accf += T / S;
            }
        }
    }

    #pragma unroll
    for (int o = 16; o; o >>= 1) accf += __shfl_xor_sync(~0u, accf, o);
    if (lane == 0) atomicAdd(&g_acc, (double)accf);

    __syncthreads();
    __threadfence();
    if (tid == 0) {
        if (atomicAdd(&g_done, 1) == (int)gridDim.x - 1) {
            double total = atomicAdd(&g_acc, 0.0);
            out[0] = (float)(-total / (double)N);
            g_acc = 0.0;
            g_counter = 0;
            g_prep_done = 0;
            g_done = 0;
            __threadfence();
        }
    }
}

// ---------------------------------------------------------------------------
extern "C" void kernel_launch(void* const* d_in, const int* in_sizes, int n_in,
                              void* d_out, int out_size) {
    const float* X           = (const float*)d_in[0];
    const float* means       = (const float*)d_in[1];
    const float* scale_tril  = (const float*)d_in[2];
    const float* log_weights = (const float*)d_in[3];
    float* out = (float*)d_out;

    int N = in_sizes[0] / D;
    int nunits = (N + UNIT - 1) / UNIT;

    cudaFuncSetAttribute(gmm_fused, cudaFuncAttributeMaxDynamicSharedMemorySize,
                         SMEM_TOTAL);
    int nsm = 148;
    cudaDeviceGetAttribute(&nsm, cudaDevAttrMultiProcessorCount, 0);

    gmm_fused<<<nsm, TPB, SMEM_TOTAL>>>(X, means, scale_tril, log_weights,
                                        out, N, nunits);
}